// round 16
// baseline (speedup 1.0000x reference)
#include <cuda_runtime.h>
#include <cuda_bf16.h>
#include <stdint.h>
#include <math.h>

#define Bb   64
#define Tt   200
#define Dd   128
#define Mm   50
#define BT   (Bb*Tt)          // 12800
#define NUMQ 1000
#define NC   8                // scan chunks
#define LL   25               // Tt / NC
#define PH   13               // k2c reduction phase length

// ---------------- scratch ----------------
__device__ float g_k[BT*Dd];
__device__ float g_v[BT*Dd];
__device__ float g_w[BT*Mm];
__device__ float g_e[BT*Dd];
__device__ float g_a[BT*Dd];
__device__ float g_read[BT*Dd];
__device__ float g_read2[BT*Dd];
__device__ float g_A[Bb*NC*Mm*Dd];  // chunk affine scale   [b][ci][m][d]
__device__ float g_B[Bb*NC*Mm*Dd];  // chunk affine offset

__device__ __forceinline__ float sigmoidf_(float x){ return 1.f/(1.f+expf(-x)); }

__device__ __forceinline__ unsigned int f2tf32(float x){
    unsigned int r;
    asm("cvt.rna.tf32.f32 %0, %1;" : "=r"(r) : "f"(x));
    return r;
}

__device__ __forceinline__ void mma_tf32(float c[4],
    unsigned int a0, unsigned int a1, unsigned int a2, unsigned int a3,
    unsigned int b0, unsigned int b1)
{
    asm volatile(
        "mma.sync.aligned.m16n8k8.row.col.f32.tf32.tf32.f32 "
        "{%0,%1,%2,%3}, {%4,%5,%6,%7}, {%8,%9}, {%0,%1,%2,%3};\n"
        : "+f"(c[0]), "+f"(c[1]), "+f"(c[2]), "+f"(c[3])
        : "r"(a0), "r"(a1), "r"(a2), "r"(a3), "r"(b0), "r"(b1));
}

// ---------------- K1: gather k/v, w logits + softmax ----------------
__global__ __launch_bounds__(256) void k1_gather(
    const int* __restrict__ q, const int* __restrict__ r, const int* __restrict__ pid,
    const float* __restrict__ pid_emb, const float* __restrict__ k_emb,
    const float* __restrict__ v_emb, const float* __restrict__ Mk)
{
    const int tid  = threadIdx.x;
    const int lane = tid & 31;
    const int wid  = tid >> 5;
    const int row0 = blockIdx.x * 16;

    __shared__ float k_s[16][Dd];        // rows 512B -> float4 aligned
    __shared__ float mk_s[Mm][132];      // 528B rows -> float4 aligned, pad 132
    __shared__ float wl[16][52];

    for (int i=tid; i<Mm*Dd; i+=256) mk_s[i/Dd][i%Dd] = Mk[i];

    for (int i=tid; i<16*Dd; i+=256){
        int rr = i >> 7, d = i & 127;
        int row = row0 + rr;
        int qi = q[row], ri = r[row], pi = pid[row];
        float pe = pid_emb[pi*Dd + d];
        float kk = k_emb[qi*Dd + d] + pe;
        float vv = v_emb[(qi + ri*NUMQ)*Dd + d] + pe;
        k_s[rr][d] = kk;
        g_k[row*Dd + d] = kk;
        g_v[row*Dd + d] = vv;
    }
    __syncthreads();

    // logits with float4 LDS
    for (int p=tid; p<16*Mm; p+=256){
        int rr = p/Mm, m = p - rr*Mm;
        const float4* mk4 = reinterpret_cast<const float4*>(&mk_s[m][0]);
        const float4* ks4 = reinterpret_cast<const float4*>(&k_s[rr][0]);
        float acc = 0.f;
        #pragma unroll 8
        for (int d4=0; d4<32; d4++){
            float4 a = mk4[d4];
            float4 b = ks4[d4];
            acc = fmaf(a.x,b.x, fmaf(a.y,b.y, fmaf(a.z,b.z, fmaf(a.w,b.w, acc))));
        }
        wl[rr][m] = acc;
    }
    __syncthreads();

    #pragma unroll
    for (int s2=0; s2<2; s2++){
        int rr  = wid*2 + s2;
        int row = row0 + rr;
        float l0 = (lane      < Mm) ? wl[rr][lane]      : -1e30f;
        float l1 = (lane + 32 < Mm) ? wl[rr][lane + 32] : -1e30f;
        float mx = fmaxf(l0, l1);
        #pragma unroll
        for (int o=16; o; o>>=1) mx = fmaxf(mx, __shfl_xor_sync(0xffffffffu, mx, o));
        float e0 = (lane      < Mm) ? expf(l0 - mx) : 0.f;
        float e1 = (lane + 32 < Mm) ? expf(l1 - mx) : 0.f;
        float ss = e0 + e1;
        #pragma unroll
        for (int o=16; o; o>>=1) ss += __shfl_xor_sync(0xffffffffu, ss, o);
        float inv = 1.f / ss;
        if (lane      < Mm) g_w[row*Mm + lane]      = e0 * inv;
        if (lane + 32 < Mm) g_w[row*Mm + lane + 32] = e1 * inv;
    }
}

// ---------------- tf32 MMA GEMM: e/a (fused), weights transposed at load ----------------
// grid (200, 2): 64 rows x 128 cols, K=128. 128 threads = 4 warps.
__global__ __launch_bounds__(128) void k_ea_mma(const float* __restrict__ eW,
                                                const float* __restrict__ aW,
                                                const float* __restrict__ e_b,
                                                const float* __restrict__ a_b)
{
    const int tid  = threadIdx.x;
    const int lane = tid & 31;
    const int w    = tid >> 5;
    const int gid  = lane >> 2;      // 0..7
    const int tig  = lane & 3;       // 0..3
    const int row0 = blockIdx.x * 64;
    const int cb   = blockIdx.y;     // 0 -> e, 1 -> a

    const float* Wsrc = (cb==0) ? eW : aW;   // [o=128][d=128] row-major

    __shared__ float actT[32][129];  // [k][row], pad 129 -> conflict-free
    __shared__ float w_s[32][129];   // [k][o]

    float c[16][4];
    #pragma unroll
    for (int nt=0; nt<16; nt++){ c[nt][0]=0.f; c[nt][1]=0.f; c[nt][2]=0.f; c[nt][3]=0.f; }

    for (int kc=0; kc<Dd; kc+=32){
        // activations: [64 rows x 32 k], transposed into actT[kk][row]
        #pragma unroll
        for (int i=0;i<4;i++){
            int lin = tid + i*128;           // 0..511
            int rr  = lin >> 3;              // 0..63
            int kg  = lin & 7;
            float4 v = *reinterpret_cast<const float4*>(&g_v[(row0+rr)*Dd + kc + kg*4]);
            actT[kg*4+0][rr] = __uint_as_float(f2tf32(v.x));
            actT[kg*4+1][rr] = __uint_as_float(f2tf32(v.y));
            actT[kg*4+2][rr] = __uint_as_float(f2tf32(v.z));
            actT[kg*4+3][rr] = __uint_as_float(f2tf32(v.w));
        }
        // weights: W[o][kc+kk] -> w_s[kk][o], transpose + tf32 at store
        #pragma unroll
        for (int i=0;i<8;i++){
            int lin = i*128 + tid;           // 0..1023
            int kg  = lin & 7;               // 0..7
            int o   = lin >> 3;              // 0..127
            float4 v = *reinterpret_cast<const float4*>(&Wsrc[o*Dd + kc + kg*4]);
            w_s[kg*4+0][o] = __uint_as_float(f2tf32(v.x));
            w_s[kg*4+1][o] = __uint_as_float(f2tf32(v.y));
            w_s[kg*4+2][o] = __uint_as_float(f2tf32(v.z));
            w_s[kg*4+3][o] = __uint_as_float(f2tf32(v.w));
        }
        __syncthreads();

        #pragma unroll
        for (int k8=0; k8<4; k8++){
            const int kb = k8*8;
            unsigned int a0 = __float_as_uint(actT[kb+tig  ][w*16+gid]);
            unsigned int a1 = __float_as_uint(actT[kb+tig  ][w*16+gid+8]);
            unsigned int a2 = __float_as_uint(actT[kb+tig+4][w*16+gid]);
            unsigned int a3 = __float_as_uint(actT[kb+tig+4][w*16+gid+8]);
            #pragma unroll
            for (int nt=0; nt<16; nt++){
                unsigned int b0 = __float_as_uint(w_s[kb+tig  ][nt*8+gid]);
                unsigned int b1 = __float_as_uint(w_s[kb+tig+4][nt*8+gid]);
                mma_tf32(c[nt], a0, a1, a2, a3, b0, b1);
            }
        }
        __syncthreads();
    }

    const float* bias = (cb==0) ? e_b : a_b;
    float* dst = (cb==0) ? g_e : g_a;
    const int r_lo = row0 + w*16 + gid;
    const int r_hi = r_lo + 8;
    #pragma unroll
    for (int nt=0; nt<16; nt++){
        int col = nt*8 + 2*tig;
        float2 bb = *reinterpret_cast<const float2*>(&bias[col]);
        float o0, o1, o2, o3;
        if (cb==0){
            o0 = sigmoidf_(c[nt][0]+bb.x); o1 = sigmoidf_(c[nt][1]+bb.y);
            o2 = sigmoidf_(c[nt][2]+bb.x); o3 = sigmoidf_(c[nt][3]+bb.y);
        } else {
            o0 = tanhf(c[nt][0]+bb.x); o1 = tanhf(c[nt][1]+bb.y);
            o2 = tanhf(c[nt][2]+bb.x); o3 = tanhf(c[nt][3]+bb.y);
        }
        *reinterpret_cast<float2*>(&dst[(size_t)r_lo*Dd + col]) = make_float2(o0, o1);
        *reinterpret_cast<float2*>(&dst[(size_t)r_hi*Dd + col]) = make_float2(o2, o3);
    }
}

// ---------------- K2a: affine composition, d-quad + m-quarter split ----------------
__global__ __launch_bounds__(256) void k2a_affine()
{
    const int ci   = blockIdx.x;
    const int b    = blockIdx.y;
    const int mq   = blockIdx.z;
    const int tid  = threadIdx.x;
    const int lane = tid & 31;
    const int wg   = tid >> 5;
    const int t0   = ci * LL;
    const int m0   = (mq < 2) ? mq*13 : 26 + (mq-2)*12;
    const int mc   = (mq < 2) ? 13 : 12;

    __shared__ float w_s[LL][16];
    for (int i=tid; i<LL*mc; i+=256){
        int tt = i / mc, mm = i - tt*mc;
        w_s[tt][mm] = g_w[((size_t)b*Tt + t0 + tt)*Mm + m0 + mm];
    }
    __syncthreads();

    float4 A[2], Bv[2];
    #pragma unroll
    for (int i=0;i<2;i++){ A[i]=make_float4(1.f,1.f,1.f,1.f); Bv[i]=make_float4(0.f,0.f,0.f,0.f); }

    const float4* eb4 = reinterpret_cast<const float4*>(g_e + ((size_t)b*Tt + t0)*Dd);
    const float4* ab4 = reinterpret_cast<const float4*>(g_a + ((size_t)b*Tt + t0)*Dd);

    #pragma unroll 5
    for (int tt=0; tt<LL; tt++){
        float4 ev = eb4[tt*32 + lane];
        float4 av = ab4[tt*32 + lane];
        #pragma unroll
        for (int i=0;i<2;i++){
            int mm = wg + 8*i;
            if (mm < mc){
                float wv = w_s[tt][mm];
                float cx = fmaf(-wv, ev.x, 1.f);
                float cy = fmaf(-wv, ev.y, 1.f);
                float cz = fmaf(-wv, ev.z, 1.f);
                float cw = fmaf(-wv, ev.w, 1.f);
                A[i].x *= cx; A[i].y *= cy; A[i].z *= cz; A[i].w *= cw;
                Bv[i].x = fmaf(cx, Bv[i].x, wv*av.x);
                Bv[i].y = fmaf(cy, Bv[i].y, wv*av.y);
                Bv[i].z = fmaf(cz, Bv[i].z, wv*av.z);
                Bv[i].w = fmaf(cw, Bv[i].w, wv*av.w);
            }
        }
    }

    size_t base = ((size_t)(b*NC + ci)*Mm)*Dd;
    #pragma unroll
    for (int i=0;i<2;i++){
        int mm = wg + 8*i;
        if (mm < mc){
            *reinterpret_cast<float4*>(&g_A[base + (size_t)(m0+mm)*Dd + lane*4]) = A[i];
            *reinterpret_cast<float4*>(&g_B[base + (size_t)(m0+mm)*Dd + lane*4]) = Bv[i];
        }
    }
}

// ---------------- K2b: chunk-start states, parallel over (m-group, b) ----------------
// Chunk-start stores use DEFAULT policy (k2c re-reads them -> keep in L2).
__global__ __launch_bounds__(256) void k2b_chunkstart(const float* __restrict__ Mv0,
                                                      float* __restrict__ out_Mv)
{
    const int mg   = blockIdx.x;
    const int b    = blockIdx.y;
    const int tid  = threadIdx.x;
    const int lane = tid & 31;
    const int wg   = tid >> 5;
    const int m    = mg*8 + wg;
    if (m >= Mm) return;

    float4 s = *reinterpret_cast<const float4*>(&Mv0[m*Dd + lane*4]);
    *reinterpret_cast<float4*>(&out_Mv[((size_t)(b*(Tt+1)) * Mm + m) * Dd + lane*4]) = s;

    #pragma unroll
    for (int ci=0; ci<NC; ci++){
        size_t off = ((size_t)(b*NC + ci)*Mm + m)*Dd + lane*4;
        float4 A  = *reinterpret_cast<const float4*>(&g_A[off]);
        float4 Bv = *reinterpret_cast<const float4*>(&g_B[off]);
        s.x = fmaf(A.x, s.x, Bv.x);
        s.y = fmaf(A.y, s.y, Bv.y);
        s.z = fmaf(A.z, s.z, Bv.z);
        s.w = fmaf(A.w, s.w, Bv.w);
        *reinterpret_cast<float4*>(&out_Mv[((size_t)(b*(Tt+1) + (ci+1)*LL) * Mm + m) * Dd + lane*4]) = s;
    }
}

// ---------------- K2c: expand chunks, d-quad STG.128, phase-reduced read ----------------
__global__ __launch_bounds__(128) void k2c_expand(float* __restrict__ out_Mv)
{
    const int ci = blockIdx.x;
    const int b  = blockIdx.y;
    const int mh = blockIdx.z;
    const int tid  = threadIdx.x;
    const int lane = tid & 31;
    const int wg   = tid >> 5;
    const int t0 = ci * LL;
    const int m0 = mh * 25;

    __shared__ float w_s[LL][28];
    __shared__ float part[4][PH][Dd];

    for (int i=tid; i<LL*25; i+=128){
        int tt = i / 25, mm = i - tt*25;
        w_s[tt][mm] = g_w[((size_t)b*Tt + t0 + tt)*Mm + m0 + mm];
    }
    __syncthreads();

    float4 mv[7];
    {
        const float* st = out_Mv + ((size_t)(b*(Tt+1) + t0) * Mm) * Dd;
        #pragma unroll
        for (int i=0;i<7;i++){
            int mm = wg + 4*i;
            mv[i] = (mm < 25) ? *reinterpret_cast<const float4*>(&st[(size_t)(m0+mm)*Dd + lane*4])
                              : make_float4(0.f,0.f,0.f,0.f);
        }
    }

    const float4* eb4 = reinterpret_cast<const float4*>(g_e + ((size_t)b*Tt + t0)*Dd);
    const float4* ab4 = reinterpret_cast<const float4*>(g_a + ((size_t)b*Tt + t0)*Dd);
    float*        rb  = ((mh==0) ? g_read : g_read2) + ((size_t)b*Tt + t0)*Dd;

    for (int ph=0; ph<2; ph++){
        const int ttA = ph*PH;
        const int ttB = (ph==0) ? PH : LL;

        for (int tt=ttA; tt<ttB; tt++){
            float4 ev = eb4[tt*32 + lane];
            float4 av = ab4[tt*32 + lane];
            float* outp = out_Mv + ((size_t)(b*(Tt+1) + t0 + tt) * Mm) * Dd;
            float4 racc = make_float4(0.f,0.f,0.f,0.f);
            #pragma unroll
            for (int i=0;i<7;i++){
                int mm = wg + 4*i;
                if (mm < 25){
                    float wv = w_s[tt][mm];
                    float4 s = mv[i];
                    racc.x = fmaf(wv, s.x, racc.x);
                    racc.y = fmaf(wv, s.y, racc.y);
                    racc.z = fmaf(wv, s.z, racc.z);
                    racc.w = fmaf(wv, s.w, racc.w);
                    if (tt > 0)
                        __stcs(reinterpret_cast<float4*>(&outp[(size_t)(m0+mm)*Dd + lane*4]), s);
                    float wex = wv * ev.x, wey = wv * ev.y, wez = wv * ev.z, wew = wv * ev.w;
                    mv[i].x = fmaf(wv, av.x, fmaf(-wex, s.x, s.x));
                    mv[i].y = fmaf(wv, av.y, fmaf(-wey, s.y, s.y));
                    mv[i].z = fmaf(wv, av.z, fmaf(-wez, s.z, s.z));
                    mv[i].w = fmaf(wv, av.w, fmaf(-wew, s.w, s.w));
                }
            }
            *reinterpret_cast<float4*>(&part[wg][tt-ttA][lane*4]) = racc;
        }
        __syncthreads();
        const int nt = ttB - ttA;
        for (int idx=tid; idx<nt*32; idx+=128){
            int tt = idx >> 5, l = idx & 31;
            float4 p0 = *reinterpret_cast<float4*>(&part[0][tt][l*4]);
            float4 p1 = *reinterpret_cast<float4*>(&part[1][tt][l*4]);
            float4 p2 = *reinterpret_cast<float4*>(&part[2][tt][l*4]);
            float4 p3 = *reinterpret_cast<float4*>(&part[3][tt][l*4]);
            float4 rs = make_float4(p0.x+p1.x+p2.x+p3.x, p0.y+p1.y+p2.y+p3.y,
                                    p0.z+p1.z+p2.z+p3.z, p0.w+p1.w+p2.w+p3.w);
            *reinterpret_cast<float4*>(&rb[(size_t)(ttA+tt)*Dd + l*4]) = rs;
        }
        __syncthreads();
    }
}

// ---------------- tf32 MMA GEMM: f + p head, weights transposed at load ----------------
// grid 200: 64 rows x 128 cols, K=256 ([read1+read2 | k]). 128 threads.
__global__ __launch_bounds__(128) void k_f_mma(const float* __restrict__ fW,
                                               const float* __restrict__ f_b,
                                               const float* __restrict__ p_W,
                                               const float* __restrict__ p_b,
                                               float* __restrict__ out_p)
{
    const int tid  = threadIdx.x;
    const int lane = tid & 31;
    const int w    = tid >> 5;
    const int gid  = lane >> 2;
    const int tig  = lane & 3;
    const int row0 = blockIdx.x * 64;

    __shared__ float actT[32][129];
    __shared__ float w_s[32][129];
    __shared__ float s_fb[Dd];
    __shared__ float s_pw[Dd];

    s_fb[tid] = f_b[tid];
    s_pw[tid] = p_W[tid];

    float c[16][4];
    #pragma unroll
    for (int nt=0; nt<16; nt++){ c[nt][0]=0.f; c[nt][1]=0.f; c[nt][2]=0.f; c[nt][3]=0.f; }

    for (int kc=0; kc<2*Dd; kc+=32){
        if (kc < Dd){
            const float* src1 = g_read  + (size_t)row0*Dd + kc;
            const float* src2 = g_read2 + (size_t)row0*Dd + kc;
            #pragma unroll
            for (int i=0;i<4;i++){
                int lin = tid + i*128;
                int rr  = lin >> 3;
                int kg  = lin & 7;
                float4 v1 = *reinterpret_cast<const float4*>(&src1[rr*Dd + kg*4]);
                float4 v2 = *reinterpret_cast<const float4*>(&src2[rr*Dd + kg*4]);
                actT[kg*4+0][rr] = __uint_as_float(f2tf32(v1.x+v2.x));
                actT[kg*4+1][rr] = __uint_as_float(f2tf32(v1.y+v2.y));
                actT[kg*4+2][rr] = __uint_as_float(f2tf32(v1.z+v2.z));
                actT[kg*4+3][rr] = __uint_as_float(f2tf32(v1.w+v2.w));
            }
        } else {
            const float* src = g_k + (size_t)row0*Dd + (kc - Dd);
            #pragma unroll
            for (int i=0;i<4;i++){
                int lin = tid + i*128;
                int rr  = lin >> 3;
                int kg  = lin & 7;
                float4 v = *reinterpret_cast<const float4*>(&src[rr*Dd + kg*4]);
                actT[kg*4+0][rr] = __uint_as_float(f2tf32(v.x));
                actT[kg*4+1][rr] = __uint_as_float(f2tf32(v.y));
                actT[kg*4+2][rr] = __uint_as_float(f2tf32(v.z));
                actT[kg*4+3][rr] = __uint_as_float(f2tf32(v.w));
            }
        }
        // weights: fW[o][kc+kk] (row length 2*Dd) -> w_s[kk][o]
        #pragma unroll
        for (int i=0;i<8;i++){
            int lin = i*128 + tid;
            int kg  = lin & 7;
            int o   = lin >> 3;
            float4 v = *reinterpret_cast<const float4*>(&fW[o*(2*Dd) + kc + kg*4]);
            w_s[kg*4+0][o] = __uint_as_float(f2tf32(v.x));
            w_s[kg*4+1][o] = __uint_as_float(f2tf32(v.y));
            w_s[kg*4+2][o] = __uint_as_float(f2tf32(v.z));
            w_s[kg*4+3][o] = __uint_as_float(f2tf32(v.w));
        }
        __syncthreads();

        #pragma unroll
        for (int k8=0; k8<4; k8++){
            const int kb = k8*8;
            unsigned int a0 = __float_as_uint(actT[kb+tig  ][w*16+gid]);
            unsigned int a1 = __float_as_uint(actT[kb+tig  ][w*16+gid+8]);
            unsigned int a2 = __float_as_uint(actT[kb+tig+4][w*16+gid]);
            unsigned int a3 = __float_as_uint(actT[kb+tig+4][w*16+gid+8]);
            #pragma unroll
            for (int nt=0; nt<16; nt++){
                unsigned int b0 = __float_as_uint(w_s[kb+tig  ][nt*8+gid]);
                unsigned int b1 = __float_as_uint(w_s[kb+tig+4][nt*8+gid]);
                mma_tf32(c[nt], a0, a1, a2, a3, b0, b1);
            }
        }
        __syncthreads();
    }

    // epilogue: p = sigmoid( sum_o pW[o]*tanh(f[o]) + pb )
    float s_lo = 0.f, s_hi = 0.f;
    #pragma unroll
    for (int nt=0; nt<16; nt++){
        int col = nt*8 + 2*tig;
        float fb0 = s_fb[col], fb1 = s_fb[col+1];
        float pw0 = s_pw[col], pw1 = s_pw[col+1];
        s_lo = fmaf(pw0, tanhf(c[nt][0]+fb0), fmaf(pw1, tanhf(c[nt][1]+fb1), s_lo));
        s_hi = fmaf(pw0, tanhf(c[nt][2]+fb0), fmaf(pw1, tanhf(c[nt][3]+fb1), s_hi));
    }
    s_lo += __shfl_xor_sync(0xffffffffu, s_lo, 1);
    s_lo += __shfl_xor_sync(0xffffffffu, s_lo, 2);
    s_hi += __shfl_xor_sync(0xffffffffu, s_hi, 1);
    s_hi += __shfl_xor_sync(0xffffffffu, s_hi, 2);
    if (tig == 0){
        float pb = p_b[0];
        out_p[row0 + w*16 + gid]     = sigmoidf_(s_lo + pb);
        out_p[row0 + w*16 + gid + 8] = sigmoidf_(s_hi + pb);
    }
}

// ---------------- launch ----------------
extern "C" void kernel_launch(void* const* d_in, const int* in_sizes, int n_in,
                              void* d_out, int out_size)
{
    const int*   q       = (const int*)  d_in[0];
    const int*   r       = (const int*)  d_in[1];
    const int*   pid     = (const int*)  d_in[2];
    const float* pid_emb = (const float*)d_in[3];
    const float* k_emb   = (const float*)d_in[4];
    const float* v_emb   = (const float*)d_in[5];
    const float* Mk      = (const float*)d_in[6];
    const float* Mv0     = (const float*)d_in[7];
    const float* f_W     = (const float*)d_in[8];
    const float* f_b     = (const float*)d_in[9];
    const float* p_W     = (const float*)d_in[10];
    const float* p_b     = (const float*)d_in[11];
    const float* e_W     = (const float*)d_in[12];
    const float* e_b     = (const float*)d_in[13];
    const float* a_W     = (const float*)d_in[14];
    const float* a_b     = (const float*)d_in[15];

    float* out_p  = (float*)d_out;              // (64, 200)
    float* out_Mv = (float*)d_out + BT;         // (64, 201, 50, 128)

    k1_gather<<<BT/16, 256>>>(q, r, pid, pid_emb, k_emb, v_emb, Mk);
    {
        dim3 gea(BT/64, 2);
        k_ea_mma<<<gea, 128>>>(e_W, a_W, e_b, a_b);
    }
    {
        dim3 g1(NC, Bb, 4);
        k2a_affine<<<g1, 256>>>();
        dim3 g2(7, Bb);
        k2b_chunkstart<<<g2, 256>>>(Mv0, out_Mv);
        dim3 g3(NC, Bb, 2);
        k2c_expand<<<g3, 128>>>(out_Mv);
    }
    k_f_mma<<<BT/64, 128>>>(f_W, f_b, p_W, p_b, out_p);
}

// round 17
// speedup vs baseline: 1.1236x; 1.1236x over previous
#include <cuda_runtime.h>
#include <cuda_bf16.h>
#include <stdint.h>
#include <math.h>

#define Bb   64
#define Tt   200
#define Dd   128
#define Mm   50
#define BT   (Bb*Tt)          // 12800
#define NUMQ 1000
#define NC   8                // scan chunks
#define LL   25               // Tt / NC
#define PH   13               // k2c reduction phase length

// ---------------- scratch ----------------
__device__ float g_k[BT*Dd];
__device__ float g_v[BT*Dd];
__device__ float g_w[BT*Mm];
__device__ float g_e[BT*Dd];
__device__ float g_a[BT*Dd];
__device__ float g_read[BT*Dd];
__device__ float g_read2[BT*Dd];
__device__ float g_Wea[Dd*2*Dd];    // [d][o] tf32-rounded: o<128 -> e_W^T, o>=128 -> a_W^T
__device__ float g_fWt[2*Dd*Dd];    // [dd(256)][o(128)] tf32-rounded
__device__ float g_A[Bb*NC*Mm*Dd];  // chunk affine scale   [b][ci][m][d]
__device__ float g_B[Bb*NC*Mm*Dd];  // chunk affine offset

__device__ __forceinline__ float sigmoidf_(float x){ return 1.f/(1.f+expf(-x)); }

__device__ __forceinline__ unsigned int f2tf32(float x){
    unsigned int r;
    asm("cvt.rna.tf32.f32 %0, %1;" : "=r"(r) : "f"(x));
    return r;
}

__device__ __forceinline__ void mma_tf32(float c[4],
    unsigned int a0, unsigned int a1, unsigned int a2, unsigned int a3,
    unsigned int b0, unsigned int b1)
{
    asm volatile(
        "mma.sync.aligned.m16n8k8.row.col.f32.tf32.tf32.f32 "
        "{%0,%1,%2,%3}, {%4,%5,%6,%7}, {%8,%9}, {%0,%1,%2,%3};\n"
        : "+f"(c[0]), "+f"(c[1]), "+f"(c[2]), "+f"(c[3])
        : "r"(a0), "r"(a1), "r"(a2), "r"(a3), "r"(b0), "r"(b1));
}

// ---------------- K0: transpose weights + tf32 round ----------------
__global__ void k0_transpose(const float* __restrict__ eW,
                             const float* __restrict__ aW, const float* __restrict__ fW){
    int tid = blockIdx.x*blockDim.x + threadIdx.x;
    int nt  = gridDim.x*blockDim.x;
    for (int i=tid; i<Dd*Dd; i+=nt){
        int o=i/Dd, d=i%Dd;
        g_Wea[d*(2*Dd)+o]    = __uint_as_float(f2tf32(eW[i]));
        g_Wea[d*(2*Dd)+Dd+o] = __uint_as_float(f2tf32(aW[i]));
    }
    for (int i=tid; i<Dd*2*Dd; i+=nt){
        int o=i/(2*Dd), dd=i%(2*Dd);
        g_fWt[dd*Dd+o] = __uint_as_float(f2tf32(fW[i]));
    }
}

// ---------------- K1: gather k/v, w logits + softmax (fp32) ----------------
__global__ __launch_bounds__(256) void k1_gather(
    const int* __restrict__ q, const int* __restrict__ r, const int* __restrict__ pid,
    const float* __restrict__ pid_emb, const float* __restrict__ k_emb,
    const float* __restrict__ v_emb, const float* __restrict__ Mk)
{
    const int tid  = threadIdx.x;
    const int lane = tid & 31;
    const int wid  = tid >> 5;
    const int row0 = blockIdx.x * 16;

    __shared__ float k_s[16][Dd];
    __shared__ float mk_s[Mm][129];
    __shared__ float wl[16][52];

    for (int i=tid; i<Mm*Dd; i+=256) mk_s[i/Dd][i%Dd] = Mk[i];

    for (int i=tid; i<16*Dd; i+=256){
        int rr = i >> 7, d = i & 127;
        int row = row0 + rr;
        int qi = q[row], ri = r[row], pi = pid[row];
        float pe = pid_emb[pi*Dd + d];
        float kk = k_emb[qi*Dd + d] + pe;
        float vv = v_emb[(qi + ri*NUMQ)*Dd + d] + pe;
        k_s[rr][d] = kk;
        g_k[row*Dd + d] = kk;
        g_v[row*Dd + d] = vv;
    }
    __syncthreads();

    for (int p=tid; p<16*Mm; p+=256){
        int rr = p/Mm, m = p - rr*Mm;
        float acc = 0.f;
        #pragma unroll 4
        for (int d=0; d<Dd; d++) acc = fmaf(mk_s[m][d], k_s[rr][d], acc);
        wl[rr][m] = acc;
    }
    __syncthreads();

    #pragma unroll
    for (int s2=0; s2<2; s2++){
        int rr  = wid*2 + s2;
        int row = row0 + rr;
        float l0 = (lane      < Mm) ? wl[rr][lane]      : -1e30f;
        float l1 = (lane + 32 < Mm) ? wl[rr][lane + 32] : -1e30f;
        float mx = fmaxf(l0, l1);
        #pragma unroll
        for (int o=16; o; o>>=1) mx = fmaxf(mx, __shfl_xor_sync(0xffffffffu, mx, o));
        float e0 = (lane      < Mm) ? expf(l0 - mx) : 0.f;
        float e1 = (lane + 32 < Mm) ? expf(l1 - mx) : 0.f;
        float ss = e0 + e1;
        #pragma unroll
        for (int o=16; o; o>>=1) ss += __shfl_xor_sync(0xffffffffu, ss, o);
        float inv = 1.f / ss;
        if (lane      < Mm) g_w[row*Mm + lane]      = e0 * inv;
        if (lane + 32 < Mm) g_w[row*Mm + lane + 32] = e1 * inv;
    }
}

// ---------------- tf32 MMA GEMM: e/a (fused) ----------------
// grid (200, 2): 64 rows x 128 cols, K=128. 128 threads = 4 warps.
__global__ __launch_bounds__(128) void k_ea_mma(const float* __restrict__ e_b,
                                                const float* __restrict__ a_b)
{
    const int tid  = threadIdx.x;
    const int lane = tid & 31;
    const int w    = tid >> 5;
    const int gid  = lane >> 2;      // 0..7
    const int tig  = lane & 3;       // 0..3
    const int row0 = blockIdx.x * 64;
    const int cb   = blockIdx.y;     // 0 -> e, 1 -> a

    __shared__ float actT[32][136];  // [k][row]
    __shared__ float w_s[32][136];   // [k][o]

    float c[16][4];
    #pragma unroll
    for (int nt=0; nt<16; nt++){ c[nt][0]=0.f; c[nt][1]=0.f; c[nt][2]=0.f; c[nt][3]=0.f; }

    for (int kc=0; kc<Dd; kc+=32){
        #pragma unroll
        for (int i=0;i<4;i++){
            int lin = tid + i*128;           // 0..511
            int rr  = lin >> 3;              // 0..63
            int kg  = lin & 7;
            float4 v = *reinterpret_cast<const float4*>(&g_v[(row0+rr)*Dd + kc + kg*4]);
            actT[kg*4+0][rr] = __uint_as_float(f2tf32(v.x));
            actT[kg*4+1][rr] = __uint_as_float(f2tf32(v.y));
            actT[kg*4+2][rr] = __uint_as_float(f2tf32(v.z));
            actT[kg*4+3][rr] = __uint_as_float(f2tf32(v.w));
        }
        #pragma unroll
        for (int i=0;i<8;i++){
            int lin = tid + i*128;
            int kk  = lin >> 5;
            int c4  = lin & 31;
            *reinterpret_cast<float4*>(&w_s[kk][c4*4]) =
                *reinterpret_cast<const float4*>(&g_Wea[(kc+kk)*(2*Dd) + cb*Dd + c4*4]);
        }
        __syncthreads();

        #pragma unroll
        for (int k8=0; k8<4; k8++){
            const int kb = k8*8;
            unsigned int a0 = __float_as_uint(actT[kb+tig  ][w*16+gid]);
            unsigned int a1 = __float_as_uint(actT[kb+tig  ][w*16+gid+8]);
            unsigned int a2 = __float_as_uint(actT[kb+tig+4][w*16+gid]);
            unsigned int a3 = __float_as_uint(actT[kb+tig+4][w*16+gid+8]);
            #pragma unroll
            for (int nt=0; nt<16; nt++){
                unsigned int b0 = __float_as_uint(w_s[kb+tig  ][nt*8+gid]);
                unsigned int b1 = __float_as_uint(w_s[kb+tig+4][nt*8+gid]);
                mma_tf32(c[nt], a0, a1, a2, a3, b0, b1);
            }
        }
        __syncthreads();
    }

    const float* bias = (cb==0) ? e_b : a_b;
    float* dst = (cb==0) ? g_e : g_a;
    const int r_lo = row0 + w*16 + gid;
    const int r_hi = r_lo + 8;
    #pragma unroll
    for (int nt=0; nt<16; nt++){
        int col = nt*8 + 2*tig;
        float2 bb = *reinterpret_cast<const float2*>(&bias[col]);
        float o0, o1, o2, o3;
        if (cb==0){
            o0 = sigmoidf_(c[nt][0]+bb.x); o1 = sigmoidf_(c[nt][1]+bb.y);
            o2 = sigmoidf_(c[nt][2]+bb.x); o3 = sigmoidf_(c[nt][3]+bb.y);
        } else {
            o0 = tanhf(c[nt][0]+bb.x); o1 = tanhf(c[nt][1]+bb.y);
            o2 = tanhf(c[nt][2]+bb.x); o3 = tanhf(c[nt][3]+bb.y);
        }
        *reinterpret_cast<float2*>(&dst[(size_t)r_lo*Dd + col]) = make_float2(o0, o1);
        *reinterpret_cast<float2*>(&dst[(size_t)r_hi*Dd + col]) = make_float2(o2, o3);
    }
}

// ---------------- K2a: affine composition, d-quad + m-quarter split ----------------
__global__ __launch_bounds__(256) void k2a_affine()
{
    const int ci   = blockIdx.x;
    const int b    = blockIdx.y;
    const int mq   = blockIdx.z;
    const int tid  = threadIdx.x;
    const int lane = tid & 31;
    const int wg   = tid >> 5;
    const int t0   = ci * LL;
    const int m0   = (mq < 2) ? mq*13 : 26 + (mq-2)*12;
    const int mc   = (mq < 2) ? 13 : 12;

    __shared__ float w_s[LL][16];
    for (int i=tid; i<LL*mc; i+=256){
        int tt = i / mc, mm = i - tt*mc;
        w_s[tt][mm] = g_w[((size_t)b*Tt + t0 + tt)*Mm + m0 + mm];
    }
    __syncthreads();

    float4 A[2], Bv[2];
    #pragma unroll
    for (int i=0;i<2;i++){ A[i]=make_float4(1.f,1.f,1.f,1.f); Bv[i]=make_float4(0.f,0.f,0.f,0.f); }

    const float4* eb4 = reinterpret_cast<const float4*>(g_e + ((size_t)b*Tt + t0)*Dd);
    const float4* ab4 = reinterpret_cast<const float4*>(g_a + ((size_t)b*Tt + t0)*Dd);

    #pragma unroll 5
    for (int tt=0; tt<LL; tt++){
        float4 ev = eb4[tt*32 + lane];
        float4 av = ab4[tt*32 + lane];
        #pragma unroll
        for (int i=0;i<2;i++){
            int mm = wg + 8*i;
            if (mm < mc){
                float wv = w_s[tt][mm];
                float cx = fmaf(-wv, ev.x, 1.f);
                float cy = fmaf(-wv, ev.y, 1.f);
                float cz = fmaf(-wv, ev.z, 1.f);
                float cw = fmaf(-wv, ev.w, 1.f);
                A[i].x *= cx; A[i].y *= cy; A[i].z *= cz; A[i].w *= cw;
                Bv[i].x = fmaf(cx, Bv[i].x, wv*av.x);
                Bv[i].y = fmaf(cy, Bv[i].y, wv*av.y);
                Bv[i].z = fmaf(cz, Bv[i].z, wv*av.z);
                Bv[i].w = fmaf(cw, Bv[i].w, wv*av.w);
            }
        }
    }

    size_t base = ((size_t)(b*NC + ci)*Mm)*Dd;
    #pragma unroll
    for (int i=0;i<2;i++){
        int mm = wg + 8*i;
        if (mm < mc){
            *reinterpret_cast<float4*>(&g_A[base + (size_t)(m0+mm)*Dd + lane*4]) = A[i];
            *reinterpret_cast<float4*>(&g_B[base + (size_t)(m0+mm)*Dd + lane*4]) = Bv[i];
        }
    }
}

// ---------------- K2b: chunk-start states, parallel over (m-group, b) ----------------
// Default-policy stores: k2c re-reads chunk starts -> keep them in L2.
__global__ __launch_bounds__(256) void k2b_chunkstart(const float* __restrict__ Mv0,
                                                      float* __restrict__ out_Mv)
{
    const int mg   = blockIdx.x;
    const int b    = blockIdx.y;
    const int tid  = threadIdx.x;
    const int lane = tid & 31;
    const int wg   = tid >> 5;
    const int m    = mg*8 + wg;
    if (m >= Mm) return;

    float4 s = *reinterpret_cast<const float4*>(&Mv0[m*Dd + lane*4]);
    *reinterpret_cast<float4*>(&out_Mv[((size_t)(b*(Tt+1)) * Mm + m) * Dd + lane*4]) = s;

    #pragma unroll
    for (int ci=0; ci<NC; ci++){
        size_t off = ((size_t)(b*NC + ci)*Mm + m)*Dd + lane*4;
        float4 A  = *reinterpret_cast<const float4*>(&g_A[off]);
        float4 Bv = *reinterpret_cast<const float4*>(&g_B[off]);
        s.x = fmaf(A.x, s.x, Bv.x);
        s.y = fmaf(A.y, s.y, Bv.y);
        s.z = fmaf(A.z, s.z, Bv.z);
        s.w = fmaf(A.w, s.w, Bv.w);
        *reinterpret_cast<float4*>(&out_Mv[((size_t)(b*(Tt+1) + (ci+1)*LL) * Mm + m) * Dd + lane*4]) = s;
    }
}

// ---------------- K2c: expand chunks, d-quad STG.128, phase-reduced read ----------------
__global__ __launch_bounds__(128) void k2c_expand(float* __restrict__ out_Mv)
{
    const int ci = blockIdx.x;
    const int b  = blockIdx.y;
    const int mh = blockIdx.z;
    const int tid  = threadIdx.x;
    const int lane = tid & 31;
    const int wg   = tid >> 5;
    const int t0 = ci * LL;
    const int m0 = mh * 25;

    __shared__ float w_s[LL][28];
    __shared__ float part[4][PH][Dd];

    for (int i=tid; i<LL*25; i+=128){
        int tt = i / 25, mm = i - tt*25;
        w_s[tt][mm] = g_w[((size_t)b*Tt + t0 + tt)*Mm + m0 + mm];
    }
    __syncthreads();

    float4 mv[7];
    {
        const float* st = out_Mv + ((size_t)(b*(Tt+1) + t0) * Mm) * Dd;
        #pragma unroll
        for (int i=0;i<7;i++){
            int mm = wg + 4*i;
            mv[i] = (mm < 25) ? *reinterpret_cast<const float4*>(&st[(size_t)(m0+mm)*Dd + lane*4])
                              : make_float4(0.f,0.f,0.f,0.f);
        }
    }

    const float4* eb4 = reinterpret_cast<const float4*>(g_e + ((size_t)b*Tt + t0)*Dd);
    const float4* ab4 = reinterpret_cast<const float4*>(g_a + ((size_t)b*Tt + t0)*Dd);
    float*        rb  = ((mh==0) ? g_read : g_read2) + ((size_t)b*Tt + t0)*Dd;

    for (int ph=0; ph<2; ph++){
        const int ttA = ph*PH;
        const int ttB = (ph==0) ? PH : LL;

        for (int tt=ttA; tt<ttB; tt++){
            float4 ev = eb4[tt*32 + lane];
            float4 av = ab4[tt*32 + lane];
            float* outp = out_Mv + ((size_t)(b*(Tt+1) + t0 + tt) * Mm) * Dd;
            float4 racc = make_float4(0.f,0.f,0.f,0.f);
            #pragma unroll
            for (int i=0;i<7;i++){
                int mm = wg + 4*i;
                if (mm < 25){
                    float wv = w_s[tt][mm];
                    float4 s = mv[i];
                    racc.x = fmaf(wv, s.x, racc.x);
                    racc.y = fmaf(wv, s.y, racc.y);
                    racc.z = fmaf(wv, s.z, racc.z);
                    racc.w = fmaf(wv, s.w, racc.w);
                    if (tt > 0)
                        __stcs(reinterpret_cast<float4*>(&outp[(size_t)(m0+mm)*Dd + lane*4]), s);
                    float wex = wv * ev.x, wey = wv * ev.y, wez = wv * ev.z, wew = wv * ev.w;
                    mv[i].x = fmaf(wv, av.x, fmaf(-wex, s.x, s.x));
                    mv[i].y = fmaf(wv, av.y, fmaf(-wey, s.y, s.y));
                    mv[i].z = fmaf(wv, av.z, fmaf(-wez, s.z, s.z));
                    mv[i].w = fmaf(wv, av.w, fmaf(-wew, s.w, s.w));
                }
            }
            *reinterpret_cast<float4*>(&part[wg][tt-ttA][lane*4]) = racc;
        }
        __syncthreads();
        const int nt = ttB - ttA;
        for (int idx=tid; idx<nt*32; idx+=128){
            int tt = idx >> 5, l = idx & 31;
            float4 p0 = *reinterpret_cast<float4*>(&part[0][tt][l*4]);
            float4 p1 = *reinterpret_cast<float4*>(&part[1][tt][l*4]);
            float4 p2 = *reinterpret_cast<float4*>(&part[2][tt][l*4]);
            float4 p3 = *reinterpret_cast<float4*>(&part[3][tt][l*4]);
            float4 rs = make_float4(p0.x+p1.x+p2.x+p3.x, p0.y+p1.y+p2.y+p3.y,
                                    p0.z+p1.z+p2.z+p3.z, p0.w+p1.w+p2.w+p3.w);
            *reinterpret_cast<float4*>(&rb[(size_t)(ttA+tt)*Dd + l*4]) = rs;
        }
        __syncthreads();
    }
}

// ---------------- tf32 MMA GEMM: f + p head, never materializes f ----------------
// grid 200: 64 rows x 128 cols, K=256 ([read1+read2 | k]). 128 threads.
__global__ __launch_bounds__(128) void k_f_mma(const float* __restrict__ f_b,
                                               const float* __restrict__ p_W,
                                               const float* __restrict__ p_b,
                                               float* __restrict__ out_p)
{
    const int tid  = threadIdx.x;
    const int lane = tid & 31;
    const int w    = tid >> 5;
    const int gid  = lane >> 2;
    const int tig  = lane & 3;
    const int row0 = blockIdx.x * 64;

    __shared__ float actT[32][136];
    __shared__ float w_s[32][136];
    __shared__ float s_fb[Dd];
    __shared__ float s_pw[Dd];

    s_fb[tid] = f_b[tid];
    s_pw[tid] = p_W[tid];

    float c[16][4];
    #pragma unroll
    for (int nt=0; nt<16; nt++){ c[nt][0]=0.f; c[nt][1]=0.f; c[nt][2]=0.f; c[nt][3]=0.f; }

    for (int kc=0; kc<2*Dd; kc+=32){
        if (kc < Dd){
            const float* src1 = g_read  + (size_t)row0*Dd + kc;
            const float* src2 = g_read2 + (size_t)row0*Dd + kc;
            #pragma unroll
            for (int i=0;i<4;i++){
                int lin = tid + i*128;
                int rr  = lin >> 3;
                int kg  = lin & 7;
                float4 v1 = *reinterpret_cast<const float4*>(&src1[rr*Dd + kg*4]);
                float4 v2 = *reinterpret_cast<const float4*>(&src2[rr*Dd + kg*4]);
                actT[kg*4+0][rr] = __uint_as_float(f2tf32(v1.x+v2.x));
                actT[kg*4+1][rr] = __uint_as_float(f2tf32(v1.y+v2.y));
                actT[kg*4+2][rr] = __uint_as_float(f2tf32(v1.z+v2.z));
                actT[kg*4+3][rr] = __uint_as_float(f2tf32(v1.w+v2.w));
            }
        } else {
            const float* src = g_k + (size_t)row0*Dd + (kc - Dd);
            #pragma unroll
            for (int i=0;i<4;i++){
                int lin = tid + i*128;
                int rr  = lin >> 3;
                int kg  = lin & 7;
                float4 v = *reinterpret_cast<const float4*>(&src[rr*Dd + kg*4]);
                actT[kg*4+0][rr] = __uint_as_float(f2tf32(v.x));
                actT[kg*4+1][rr] = __uint_as_float(f2tf32(v.y));
                actT[kg*4+2][rr] = __uint_as_float(f2tf32(v.z));
                actT[kg*4+3][rr] = __uint_as_float(f2tf32(v.w));
            }
        }
        #pragma unroll
        for (int i=0;i<8;i++){
            int lin = tid + i*128;
            int kk  = lin >> 5;
            int c4  = lin & 31;
            *reinterpret_cast<float4*>(&w_s[kk][c4*4]) =
                *reinterpret_cast<const float4*>(&g_fWt[(kc+kk)*Dd + c4*4]);
        }
        __syncthreads();

        #pragma unroll
        for (int k8=0; k8<4; k8++){
            const int kb = k8*8;
            unsigned int a0 = __float_as_uint(actT[kb+tig  ][w*16+gid]);
            unsigned int a1 = __float_as_uint(actT[kb+tig  ][w*16+gid+8]);
            unsigned int a2 = __float_as_uint(actT[kb+tig+4][w*16+gid]);
            unsigned int a3 = __float_as_uint(actT[kb+tig+4][w*16+gid+8]);
            #pragma unroll
            for (int nt=0; nt<16; nt++){
                unsigned int b0 = __float_as_uint(w_s[kb+tig  ][nt*8+gid]);
                unsigned int b1 = __float_as_uint(w_s[kb+tig+4][nt*8+gid]);
                mma_tf32(c[nt], a0, a1, a2, a3, b0, b1);
            }
        }
        __syncthreads();
    }

    float s_lo = 0.f, s_hi = 0.f;
    #pragma unroll
    for (int nt=0; nt<16; nt++){
        int col = nt*8 + 2*tig;
        float fb0 = s_fb[col], fb1 = s_fb[col+1];
        float pw0 = s_pw[col], pw1 = s_pw[col+1];
        s_lo = fmaf(pw0, tanhf(c[nt][0]+fb0), fmaf(pw1, tanhf(c[nt][1]+fb1), s_lo));
        s_hi = fmaf(pw0, tanhf(c[nt][2]+fb0), fmaf(pw1, tanhf(c[nt][3]+fb1), s_hi));
    }
    s_lo += __shfl_xor_sync(0xffffffffu, s_lo, 1);
    s_lo += __shfl_xor_sync(0xffffffffu, s_lo, 2);
    s_hi += __shfl_xor_sync(0xffffffffu, s_hi, 1);
    s_hi += __shfl_xor_sync(0xffffffffu, s_hi, 2);
    if (tig == 0){
        float pb = p_b[0];
        out_p[row0 + w*16 + gid]     = sigmoidf_(s_lo + pb);
        out_p[row0 + w*16 + gid + 8] = sigmoidf_(s_hi + pb);
    }
}

// ---------------- launch ----------------
extern "C" void kernel_launch(void* const* d_in, const int* in_sizes, int n_in,
                              void* d_out, int out_size)
{
    const int*   q       = (const int*)  d_in[0];
    const int*   r       = (const int*)  d_in[1];
    const int*   pid     = (const int*)  d_in[2];
    const float* pid_emb = (const float*)d_in[3];
    const float* k_emb   = (const float*)d_in[4];
    const float* v_emb   = (const float*)d_in[5];
    const float* Mk      = (const float*)d_in[6];
    const float* Mv0     = (const float*)d_in[7];
    const float* f_W     = (const float*)d_in[8];
    const float* f_b     = (const float*)d_in[9];
    const float* p_W     = (const float*)d_in[10];
    const float* p_b     = (const float*)d_in[11];
    const float* e_W     = (const float*)d_in[12];
    const float* e_b     = (const float*)d_in[13];
    const float* a_W     = (const float*)d_in[14];
    const float* a_b     = (const float*)d_in[15];

    float* out_p  = (float*)d_out;              // (64, 200)
    float* out_Mv = (float*)d_out + BT;         // (64, 201, 50, 128)

    k0_transpose<<<256, 256>>>(e_W, a_W, f_W);
    k1_gather<<<BT/16, 256>>>(q, r, pid, pid_emb, k_emb, v_emb, Mk);
    {
        dim3 gea(BT/64, 2);
        k_ea_mma<<<gea, 128>>>(e_b, a_b);
    }
    {
        dim3 g1(NC, Bb, 4);
        k2a_affine<<<g1, 256>>>();
        dim3 g2(7, Bb);
        k2b_chunkstart<<<g2, 256>>>(Mv0, out_Mv);
        dim3 g3(NC, Bb, 2);
        k2c_expand<<<g3, 128>>>(out_Mv);
    }
    k_f_mma<<<BT/64, 128>>>(f_b, p_W, p_b, out_p);
}